// round 1
// baseline (speedup 1.0000x reference)
#include <cuda_runtime.h>
#include <math.h>

#define B_   8
#define L_   1024
#define D_   512
#define H_   8
#define DK_  64
#define DFF_ 2048
#define M_   (B_*L_)        // 8192 rows of the token stream

// ---------------- device scratch (static: no runtime allocation) ----------------
__device__ float g_q  [B_*H_*L_*DK_];            // (B,H,L,DK)
__device__ float g_k  [B_*H_*L_*DK_];
__device__ float g_v  [B_*H_*L_*DK_];
__device__ float g_S  [(size_t)B_*H_*L_*L_];     // (B,H,L,L) scores / probs, 256 MB
__device__ float g_ctx[M_*D_];                   // attention context in (B,L,D)
__device__ float g_bufA[M_*D_];
__device__ float g_bufB[M_*D_];
__device__ float g_ff [M_*DFF_];                 // FF hidden, 64 MB

// ---------------- GEMM epilogue modes ----------------
enum {
    EP_BIAS = 0,       // C[m*N+n] = acc + bias[n]
    EP_QKV = 1,        // permuted write to (B,H,L,DK), + bias
    EP_BIAS_RES = 2,   // + bias[n] + res[m*N+n]
    EP_GELU = 3,       // gelu(acc + bias[n])  (exact erf)
    EP_SCORE = 4,      // acc*0.125 - 0.1*|m-n|, batched write to g_S
    EP_CTX = 5         // batched write to (B,L,D) context
};

// ---------------------------------------------------------------------------
// Register-tiled fp32 GEMM: C = A * op(B)
//   A: M x K, row-major, lda        (M = gridDim.y * 128, exact)
//   TRANSB=true : B is N x K row-major (ldb = row stride)  -> C = A * B^T
//   TRANSB=false: B is K x N row-major (ldb = row stride)  -> C = A * B
// Tile: BM=128, BN=64, BK=16, 256 threads, 8x4 accum per thread.
// All of M,N multiples of tile, K multiple of 16 (true for every call here).
// ---------------------------------------------------------------------------
template<bool TRANSB, int EP>
__global__ void __launch_bounds__(256)
gemm_k(const float* __restrict__ A, const float* __restrict__ Bm,
       const float* __restrict__ bias, const float* __restrict__ res,
       float* __restrict__ C,
       int N, int K, int lda, int ldb,
       long sAb, long sBb)
{
    __shared__ float As[16][132];   // [k][m], padded (132*4B = 16B-aligned rows)
    __shared__ float Bs[16][68];    // [k][n], padded (272B rows, 16B-aligned)

    const int z  = blockIdx.z;
    const float* Ab = A  + (long)z * sAb;
    const float* Bb = Bm + (long)z * sBb;
    const int by = blockIdx.y, bx = blockIdx.x;
    const int tid = threadIdx.x;
    const int tx = tid & 15;        // n-group (4 cols)
    const int ty = tid >> 4;        // m-group (8 rows)

    float acc[8][4];
#pragma unroll
    for (int i = 0; i < 8; i++)
#pragma unroll
        for (int j = 0; j < 4; j++) acc[i][j] = 0.f;

    const int nTiles = K >> 4;
    for (int kt = 0; kt < nTiles; kt++) {
        const int k0 = kt << 4;
        // ---- load A tile 128x16 (2 float4 / thread), store transposed ----
#pragma unroll
        for (int e = 0; e < 2; e++) {
            int idx = tid + e * 256;
            int row = idx >> 2;
            int kq  = (idx & 3) << 2;
            float4 av = *(const float4*)(Ab + (long)(by * 128 + row) * lda + k0 + kq);
            As[kq + 0][row] = av.x;
            As[kq + 1][row] = av.y;
            As[kq + 2][row] = av.z;
            As[kq + 3][row] = av.w;
        }
        // ---- load B tile ----
        if (TRANSB) {
            int row = tid >> 2;           // n
            int kq  = (tid & 3) << 2;
            float4 bv = *(const float4*)(Bb + (long)(bx * 64 + row) * ldb + k0 + kq);
            Bs[kq + 0][row] = bv.x;
            Bs[kq + 1][row] = bv.y;
            Bs[kq + 2][row] = bv.z;
            Bs[kq + 3][row] = bv.w;
        } else {
            int kk = tid >> 4;
            int nq = (tid & 15) << 2;
            float4 bv = *(const float4*)(Bb + (long)(k0 + kk) * ldb + bx * 64 + nq);
            *(float4*)&Bs[kk][nq] = bv;
        }
        __syncthreads();
        // ---- compute ----
#pragma unroll
        for (int kk = 0; kk < 16; kk++) {
            float a[8], b[4];
            float4 a0 = *(float4*)&As[kk][ty * 8];
            float4 a1 = *(float4*)&As[kk][ty * 8 + 4];
            a[0]=a0.x; a[1]=a0.y; a[2]=a0.z; a[3]=a0.w;
            a[4]=a1.x; a[5]=a1.y; a[6]=a1.z; a[7]=a1.w;
            float4 b0 = *(float4*)&Bs[kk][tx * 4];
            b[0]=b0.x; b[1]=b0.y; b[2]=b0.z; b[3]=b0.w;
#pragma unroll
            for (int i = 0; i < 8; i++)
#pragma unroll
                for (int j = 0; j < 4; j++)
                    acc[i][j] = fmaf(a[i], b[j], acc[i][j]);
        }
        __syncthreads();
    }

    // ---- epilogue ----
    const int m0 = by * 128 + ty * 8;
    const int n0 = bx * 64 + tx * 4;

#pragma unroll
    for (int i = 0; i < 8; i++) {
        const int mm = m0 + i;
        float4 v = make_float4(acc[i][0], acc[i][1], acc[i][2], acc[i][3]);

        if (EP == EP_SCORE) {
            v.x = v.x * 0.125f - 0.1f * fabsf((float)(mm - (n0 + 0)));
            v.y = v.y * 0.125f - 0.1f * fabsf((float)(mm - (n0 + 1)));
            v.z = v.z * 0.125f - 0.1f * fabsf((float)(mm - (n0 + 2)));
            v.w = v.w * 0.125f - 0.1f * fabsf((float)(mm - (n0 + 3)));
            *(float4*)(C + (long)z * L_ * L_ + (long)mm * L_ + n0) = v;
        } else if (EP == EP_QKV) {
            float4 bb = *(const float4*)(bias + n0);
            v.x += bb.x; v.y += bb.y; v.z += bb.z; v.w += bb.w;
            int b = mm >> 10, l = mm & 1023;
            int h = n0 >> 6, dk = n0 & 63;
            *(float4*)(C + ((long)(b * H_ + h) * L_ + l) * DK_ + dk) = v;
        } else if (EP == EP_CTX) {
            int b = z >> 3, h = z & 7;
            *(float4*)(C + ((long)b * L_ + mm) * D_ + h * DK_ + n0) = v;
        } else if (EP == EP_BIAS) {
            float4 bb = *(const float4*)(bias + n0);
            v.x += bb.x; v.y += bb.y; v.z += bb.z; v.w += bb.w;
            *(float4*)(C + (long)mm * N + n0) = v;
        } else if (EP == EP_BIAS_RES) {
            float4 bb = *(const float4*)(bias + n0);
            float4 rr = *(const float4*)(res + (long)mm * N + n0);
            v.x += bb.x + rr.x; v.y += bb.y + rr.y;
            v.z += bb.z + rr.z; v.w += bb.w + rr.w;
            *(float4*)(C + (long)mm * N + n0) = v;
        } else if (EP == EP_GELU) {
            float4 bb = *(const float4*)(bias + n0);
            float t0 = v.x + bb.x, t1 = v.y + bb.y, t2 = v.z + bb.z, t3 = v.w + bb.w;
            v.x = 0.5f * t0 * (1.f + erff(t0 * 0.70710678118654752f));
            v.y = 0.5f * t1 * (1.f + erff(t1 * 0.70710678118654752f));
            v.z = 0.5f * t2 * (1.f + erff(t2 * 0.70710678118654752f));
            v.w = 0.5f * t3 * (1.f + erff(t3 * 0.70710678118654752f));
            *(float4*)(C + (long)mm * N + n0) = v;
        }
    }
}

// ---------------------------------------------------------------------------
// Row softmax over L_=1024 elements. One block (256 thr, 4 elems/thr) per row.
// ---------------------------------------------------------------------------
__global__ void __launch_bounds__(256)
softmax_k(float* __restrict__ S)
{
    const long row = blockIdx.x;
    float* p = S + row * (long)L_;
    const int tid = threadIdx.x;
    __shared__ float red[8];

    float4 x = *(float4*)(p + (tid << 2));

    // block max
    float mx = fmaxf(fmaxf(x.x, x.y), fmaxf(x.z, x.w));
#pragma unroll
    for (int o = 16; o; o >>= 1) mx = fmaxf(mx, __shfl_xor_sync(0xffffffffu, mx, o));
    if ((tid & 31) == 0) red[tid >> 5] = mx;
    __syncthreads();
    if (tid == 0) {
        float t = red[0];
#pragma unroll
        for (int i = 1; i < 8; i++) t = fmaxf(t, red[i]);
        red[0] = t;
    }
    __syncthreads();
    mx = red[0];
    __syncthreads();

    float e0 = __expf(x.x - mx), e1 = __expf(x.y - mx);
    float e2 = __expf(x.z - mx), e3 = __expf(x.w - mx);
    float s = e0 + e1 + e2 + e3;
#pragma unroll
    for (int o = 16; o; o >>= 1) s += __shfl_xor_sync(0xffffffffu, s, o);
    if ((tid & 31) == 0) red[tid >> 5] = s;
    __syncthreads();
    if (tid == 0) {
        float t = 0.f;
#pragma unroll
        for (int i = 1; i < 8; i++) t += red[i];
        red[0] += t;
    }
    __syncthreads();
    const float inv = 1.0f / red[0];

    *(float4*)(p + (tid << 2)) = make_float4(e0 * inv, e1 * inv, e2 * inv, e3 * inv);
}

// ---------------------------------------------------------------------------
// Fused moving_avg (window 25, zero-pad 12, count_include_pad) + LayerNorm.
// One block = one batch's 16 consecutive L-rows. 256 threads. 32 KB smem.
// ---------------------------------------------------------------------------
__global__ void __launch_bounds__(256)
mvln_k(const float* __restrict__ X, float* __restrict__ Y,
       const float* __restrict__ g, const float* __restrict__ b)
{
    __shared__ float tr[16][D_];
    const int bidx = blockIdx.x;          // 0 .. B_*L_/16 - 1
    const int bb = bidx >> 6;             // batch (64 tiles per batch)
    const int l0 = (bidx & 63) * 16;
    const float* Xb = X + (long)bb * L_ * D_;
    const int tid = threadIdx.x;

    // trend: 16 rows x 128 float4-groups = 2048 tasks
    for (int task = tid; task < 16 * 128; task += 256) {
        const int r  = task >> 7;
        const int dg = task & 127;
        const int l  = l0 + r;
        float4 s = make_float4(0.f, 0.f, 0.f, 0.f);
        const int j0 = l - 12;
#pragma unroll
        for (int j = 0; j < 25; j++) {
            const int ll = j0 + j;
            if (ll >= 0 && ll < L_) {
                float4 xv = *(const float4*)(Xb + (long)ll * D_ + (dg << 2));
                s.x += xv.x; s.y += xv.y; s.z += xv.z; s.w += xv.w;
            }
        }
        const float inv = 1.f / 25.f;
        *(float4*)&tr[r][dg << 2] = make_float4(s.x * inv, s.y * inv, s.z * inv, s.w * inv);
    }
    __syncthreads();

    // LayerNorm: warp w handles rows 2w and 2w+1
    const int wid = tid >> 5, lane = tid & 31;
#pragma unroll
    for (int rr = 0; rr < 2; rr++) {
        const int r = wid * 2 + rr;
        float sum = 0.f, sq = 0.f;
        for (int d = lane; d < D_; d += 32) {
            float v = tr[r][d];
            sum += v; sq += v * v;
        }
#pragma unroll
        for (int o = 16; o; o >>= 1) {
            sum += __shfl_xor_sync(0xffffffffu, sum, o);
            sq  += __shfl_xor_sync(0xffffffffu, sq, o);
        }
        const float mu   = sum * (1.f / D_);
        const float var  = sq * (1.f / D_) - mu * mu;
        const float rstd = rsqrtf(var + 1e-5f);
        float* Yo = Y + ((long)bb * L_ + l0 + r) * D_;
        for (int d = lane; d < D_; d += 32)
            Yo[d] = (tr[r][d] - mu) * rstd * g[d] + b[d];
    }
}

// ---------------------------------------------------------------------------
extern "C" void kernel_launch(void* const* d_in, const int* in_sizes, int n_in,
                              void* d_out, int out_size)
{
    (void)in_sizes; (void)n_in; (void)out_size;
    const float* x     = (const float*)d_in[0];
    const float* enc   = (const float*)d_in[1];
    const float* sa_Wq = (const float*)d_in[2];  const float* sa_bq = (const float*)d_in[3];
    const float* sa_Wk = (const float*)d_in[4];  const float* sa_bk = (const float*)d_in[5];
    const float* sa_Wv = (const float*)d_in[6];  const float* sa_bv = (const float*)d_in[7];
    const float* sa_Wo = (const float*)d_in[8];  const float* sa_bo = (const float*)d_in[9];
    const float* ca_Wq = (const float*)d_in[10]; const float* ca_bq = (const float*)d_in[11];
    const float* ca_Wk = (const float*)d_in[12]; const float* ca_bk = (const float*)d_in[13];
    const float* ca_Wv = (const float*)d_in[14]; const float* ca_bv = (const float*)d_in[15];
    const float* ca_Wo = (const float*)d_in[16]; const float* ca_bo = (const float*)d_in[17];
    const float* ff_W1 = (const float*)d_in[18]; const float* ff_b1 = (const float*)d_in[19];
    const float* ff_W2 = (const float*)d_in[20]; const float* ff_b2 = (const float*)d_in[21];
    const float* n1_g  = (const float*)d_in[22]; const float* n1_b  = (const float*)d_in[23];
    const float* n2_g  = (const float*)d_in[24]; const float* n2_b  = (const float*)d_in[25];
    const float* n3_g  = (const float*)d_in[26]; const float* n3_b  = (const float*)d_in[27];
    float* out = (float*)d_out;

    float *q, *k, *v, *S, *ctx, *bufA, *bufB, *ff;
    cudaGetSymbolAddress((void**)&q,    g_q);
    cudaGetSymbolAddress((void**)&k,    g_k);
    cudaGetSymbolAddress((void**)&v,    g_v);
    cudaGetSymbolAddress((void**)&S,    g_S);
    cudaGetSymbolAddress((void**)&ctx,  g_ctx);
    cudaGetSymbolAddress((void**)&bufA, g_bufA);
    cudaGetSymbolAddress((void**)&bufB, g_bufB);
    cudaGetSymbolAddress((void**)&ff,   g_ff);

    const dim3 thr(256);
    const dim3 gProj(D_ / 64, M_ / 128, 1);       // (8, 64)
    const dim3 gFF1(DFF_ / 64, M_ / 128, 1);      // (32, 64)
    const dim3 gScore(L_ / 64, L_ / 128, B_ * H_); // (16, 8, 64)
    const dim3 gPV(1, L_ / 128, B_ * H_);          // (1, 8, 64)
    const dim3 gSm(B_ * H_ * L_, 1, 1);            // 65536
    const dim3 gMv(B_ * L_ / 16, 1, 1);            // 512

    // ===================== self-attention =====================
    gemm_k<true, EP_QKV><<<gProj, thr>>>(x, sa_Wq, sa_bq, nullptr, q, D_, D_, D_, D_, 0, 0);
    gemm_k<true, EP_QKV><<<gProj, thr>>>(x, sa_Wk, sa_bk, nullptr, k, D_, D_, D_, D_, 0, 0);
    gemm_k<true, EP_QKV><<<gProj, thr>>>(x, sa_Wv, sa_bv, nullptr, v, D_, D_, D_, D_, 0, 0);
    gemm_k<true, EP_SCORE><<<gScore, thr>>>(q, k, nullptr, nullptr, S,
                                            L_, DK_, DK_, DK_,
                                            (long)L_ * DK_, (long)L_ * DK_);
    softmax_k<<<gSm, thr>>>(S);
    gemm_k<false, EP_CTX><<<gPV, thr>>>(S, v, nullptr, nullptr, ctx,
                                        DK_, L_, L_, DK_,
                                        (long)L_ * L_, (long)L_ * DK_);
    gemm_k<true, EP_BIAS_RES><<<gProj, thr>>>(ctx, sa_Wo, sa_bo, x, bufA, D_, D_, D_, D_, 0, 0);
    mvln_k<<<gMv, thr>>>(bufA, bufB, n1_g, n1_b);

    // ===================== cross-attention =====================
    gemm_k<true, EP_QKV><<<gProj, thr>>>(bufB, ca_Wq, ca_bq, nullptr, q, D_, D_, D_, D_, 0, 0);
    gemm_k<true, EP_QKV><<<gProj, thr>>>(enc,  ca_Wk, ca_bk, nullptr, k, D_, D_, D_, D_, 0, 0);
    gemm_k<true, EP_QKV><<<gProj, thr>>>(enc,  ca_Wv, ca_bv, nullptr, v, D_, D_, D_, D_, 0, 0);
    gemm_k<true, EP_SCORE><<<gScore, thr>>>(q, k, nullptr, nullptr, S,
                                            L_, DK_, DK_, DK_,
                                            (long)L_ * DK_, (long)L_ * DK_);
    softmax_k<<<gSm, thr>>>(S);
    gemm_k<false, EP_CTX><<<gPV, thr>>>(S, v, nullptr, nullptr, ctx,
                                        DK_, L_, L_, DK_,
                                        (long)L_ * L_, (long)L_ * DK_);
    gemm_k<true, EP_BIAS_RES><<<gProj, thr>>>(ctx, ca_Wo, ca_bo, bufB, bufA, D_, D_, D_, D_, 0, 0);
    mvln_k<<<gMv, thr>>>(bufA, bufB, n2_g, n2_b);

    // ===================== feed-forward =====================
    gemm_k<true, EP_GELU><<<gFF1, thr>>>(bufB, ff_W1, ff_b1, nullptr, ff,
                                         DFF_, D_, D_, D_, 0, 0);
    gemm_k<true, EP_BIAS_RES><<<gProj, thr>>>(ff, ff_W2, ff_b2, bufB, bufA,
                                              D_, DFF_, DFF_, DFF_, 0, 0);
    mvln_k<<<gMv, thr>>>(bufA, out, n3_g, n3_b);
}

// round 2
// speedup vs baseline: 2.0986x; 2.0986x over previous
#include <cuda_runtime.h>
#include <math.h>
#include <stdint.h>

#define B_   8
#define L_   1024
#define D_   512
#define H_   8
#define DK_  64
#define DFF_ 2048
#define M_   (B_*L_)

// ---------------- device scratch (static: no runtime allocation) ----------------
__device__ float g_q  [B_*H_*L_*DK_];            // (B,H,L,DK)
__device__ float g_k  [B_*H_*L_*DK_];
__device__ float g_vt [B_*H_*DK_*L_];            // (B,H,DK,L)  V transposed
__device__ float g_S  [(size_t)B_*H_*L_*L_];     // (B,H,L,L) scores / probs
__device__ float g_ctx[M_*D_];
__device__ float g_bufA[M_*D_];
__device__ float g_bufB[M_*D_];
__device__ float g_ff [M_*DFF_];

// ---------------- epilogue modes ----------------
enum {
    EP_QKV = 0,      // +bias, permuted write to (B,H,L,DK)
    EP_QKV_VT = 1,   // +bias, transposed write to (B,H,DK,L)
    EP_SCORE = 2,    // acc*0.125 - 0.1*|m-n| -> S[z]
    EP_CTX = 3,      // batched write to (B,L,D) context
    EP_BIAS_RES = 4, // +bias +res
    EP_GELU = 5      // gelu(acc+bias), exact erf
};

// ---------------- PTX helpers ----------------
__device__ __forceinline__ uint32_t f2tf(float f) {
    uint32_t u;
    asm("cvt.rna.tf32.f32 %0, %1;" : "=r"(u) : "f"(f));
    return u;
}
__device__ __forceinline__ void mma8(float* d, const uint32_t* a, const uint32_t* b) {
    asm volatile(
        "mma.sync.aligned.m16n8k8.row.col.f32.tf32.tf32.f32 "
        "{%0,%1,%2,%3}, {%4,%5,%6,%7}, {%8,%9}, {%0,%1,%2,%3};"
        : "+f"(d[0]), "+f"(d[1]), "+f"(d[2]), "+f"(d[3])
        : "r"(a[0]), "r"(a[1]), "r"(a[2]), "r"(a[3]), "r"(b[0]), "r"(b[1]));
}
__device__ __forceinline__ void cpa16(uint32_t dst, const float* src) {
    asm volatile("cp.async.ca.shared.global [%0], [%1], 16;" :: "r"(dst), "l"(src));
}
#define CP_COMMIT() asm volatile("cp.async.commit_group;")
#define CP_WAIT(n)  asm volatile("cp.async.wait_group %0;" :: "n"(n))

// ---------------------------------------------------------------------------
// tf32 tensor-core GEMM: C = A * B^T
//   A: M x K row-major (lda). B: N x K row-major (ldb). All tiles exact.
// Tile BM=128, BN=64, BK=16. 256 thr = 8 warps (4m x 2n), warp tile 32x32.
// cp.async double-buffered smem, stride-20 pad (conflict-free fragment LDS).
// ---------------------------------------------------------------------------
template<int EP>
__global__ void __launch_bounds__(256)
gemm_tc(const float* __restrict__ A, const float* __restrict__ Bm,
        const float* __restrict__ bias, const float* __restrict__ res,
        float* __restrict__ C,
        int N, int K, int lda, int ldb,
        long sAb, long sBb)
{
    __shared__ float As[2][128][20];
    __shared__ float Bs[2][64][20];

    const int z  = blockIdx.z;
    const float* Ab = A  + (long)z * sAb;
    const float* Bb = Bm + (long)z * sBb;
    const int by = blockIdx.y, bx = blockIdx.x;
    const int tid  = threadIdx.x;
    const int lane = tid & 31;
    const int warp = tid >> 5;
    const int wm = warp & 3;        // 0..3
    const int wn = warp >> 2;       // 0..1

    const uint32_t sA = (uint32_t)__cvta_generic_to_shared(&As[0][0][0]);
    const uint32_t sB = (uint32_t)__cvta_generic_to_shared(&Bs[0][0][0]);

    float acc[2][4][4];
#pragma unroll
    for (int mi = 0; mi < 2; mi++)
#pragma unroll
        for (int ni = 0; ni < 4; ni++)
#pragma unroll
            for (int r = 0; r < 4; r++) acc[mi][ni][r] = 0.f;

    // per-thread load coords
    const int arow0 = tid >> 2;           // 0..63   (A: 2 f4/thread)
    const int akq   = (tid & 3) << 2;
    const int brow  = tid >> 2;           // 0..63   (B: 1 f4/thread)
    const int bkq   = (tid & 3) << 2;

    const int nT = K >> 4;

    // ---- prologue: stage 0 ----
    {
        const int k0 = 0;
#pragma unroll
        for (int e = 0; e < 2; e++) {
            int row = arow0 + e * 64;
            cpa16(sA + (uint32_t)((row * 20 + akq) * 4),
                  Ab + (long)(by * 128 + row) * lda + k0 + akq);
        }
        cpa16(sB + (uint32_t)((brow * 20 + bkq) * 4),
              Bb + (long)(bx * 64 + brow) * ldb + k0 + bkq);
        CP_COMMIT();
    }

    for (int kt = 0; kt < nT; kt++) {
        const int st = kt & 1;
        if (kt + 1 < nT) {
            const int ns = st ^ 1;
            const int k0 = (kt + 1) << 4;
#pragma unroll
            for (int e = 0; e < 2; e++) {
                int row = arow0 + e * 64;
                cpa16(sA + (uint32_t)(((ns * 128 + row) * 20 + akq) * 4),
                      Ab + (long)(by * 128 + row) * lda + k0 + akq);
            }
            cpa16(sB + (uint32_t)(((ns * 64 + brow) * 20 + bkq) * 4),
                  Bb + (long)(bx * 64 + brow) * ldb + k0 + bkq);
            CP_COMMIT();
            CP_WAIT(1);
        } else {
            CP_WAIT(0);
        }
        __syncthreads();

        // ---- compute this stage: 2 k8-steps ----
#pragma unroll
        for (int ks = 0; ks < 2; ks++) {
            const int kc = (ks << 3) + (lane & 3);
            uint32_t afr[2][4], bfr[4][2];
#pragma unroll
            for (int mi = 0; mi < 2; mi++) {
                const int r = wm * 32 + mi * 16 + (lane >> 2);
                afr[mi][0] = f2tf(As[st][r][kc]);
                afr[mi][1] = f2tf(As[st][r + 8][kc]);
                afr[mi][2] = f2tf(As[st][r][kc + 4]);
                afr[mi][3] = f2tf(As[st][r + 8][kc + 4]);
            }
#pragma unroll
            for (int ni = 0; ni < 4; ni++) {
                const int r = wn * 32 + ni * 8 + (lane >> 2);
                bfr[ni][0] = f2tf(Bs[st][r][kc]);
                bfr[ni][1] = f2tf(Bs[st][r][kc + 4]);
            }
#pragma unroll
            for (int mi = 0; mi < 2; mi++)
#pragma unroll
                for (int ni = 0; ni < 4; ni++)
                    mma8(acc[mi][ni], afr[mi], bfr[ni]);
        }
        __syncthreads();
    }

    // ---- epilogue ----
#pragma unroll
    for (int mi = 0; mi < 2; mi++) {
#pragma unroll
        for (int ni = 0; ni < 4; ni++) {
            const int m = by * 128 + wm * 32 + mi * 16 + (lane >> 2);
            const int n = bx * 64 + wn * 32 + ni * 8 + ((lane & 3) << 1);
            float d0 = acc[mi][ni][0], d1 = acc[mi][ni][1];
            float d2 = acc[mi][ni][2], d3 = acc[mi][ni][3];

            if (EP == EP_SCORE) {
                float* Cz = C + (long)z * L_ * L_;
                float v0 = d0 * 0.125f - 0.1f * fabsf((float)(m - n));
                float v1 = d1 * 0.125f - 0.1f * fabsf((float)(m - n - 1));
                float v2 = d2 * 0.125f - 0.1f * fabsf((float)(m + 8 - n));
                float v3 = d3 * 0.125f - 0.1f * fabsf((float)(m + 8 - n - 1));
                *(float2*)(Cz + (long)m * L_ + n)       = make_float2(v0, v1);
                *(float2*)(Cz + (long)(m + 8) * L_ + n) = make_float2(v2, v3);
            } else if (EP == EP_QKV) {
                float2 bb = *(const float2*)(bias + n);
                const int h = n >> 6, dk = n & 63;
                {
                    int b = m >> 10, l = m & 1023;
                    *(float2*)(C + ((long)(b * H_ + h) * L_ + l) * DK_ + dk) =
                        make_float2(d0 + bb.x, d1 + bb.y);
                }
                {
                    int mm = m + 8;
                    int b = mm >> 10, l = mm & 1023;
                    *(float2*)(C + ((long)(b * H_ + h) * L_ + l) * DK_ + dk) =
                        make_float2(d2 + bb.x, d3 + bb.y);
                }
            } else if (EP == EP_QKV_VT) {
                float2 bb = *(const float2*)(bias + n);
                const int h = n >> 6, dk = n & 63;
                {
                    int b = m >> 10, l = m & 1023;
                    long base = ((long)(b * H_ + h) * DK_ + dk) * L_ + l;
                    C[base]      = d0 + bb.x;
                    C[base + L_] = d1 + bb.y;
                }
                {
                    int mm = m + 8;
                    int b = mm >> 10, l = mm & 1023;
                    long base = ((long)(b * H_ + h) * DK_ + dk) * L_ + l;
                    C[base]      = d2 + bb.x;
                    C[base + L_] = d3 + bb.y;
                }
            } else if (EP == EP_CTX) {
                const int b = z >> 3, h = z & 7;
                *(float2*)(C + ((long)b * L_ + m) * D_ + h * DK_ + n) =
                    make_float2(d0, d1);
                *(float2*)(C + ((long)b * L_ + m + 8) * D_ + h * DK_ + n) =
                    make_float2(d2, d3);
            } else if (EP == EP_BIAS_RES) {
                float2 bb = *(const float2*)(bias + n);
                float2 r0 = *(const float2*)(res + (long)m * N + n);
                float2 r1 = *(const float2*)(res + (long)(m + 8) * N + n);
                *(float2*)(C + (long)m * N + n) =
                    make_float2(d0 + bb.x + r0.x, d1 + bb.y + r0.y);
                *(float2*)(C + (long)(m + 8) * N + n) =
                    make_float2(d2 + bb.x + r1.x, d3 + bb.y + r1.y);
            } else if (EP == EP_GELU) {
                float2 bb = *(const float2*)(bias + n);
                float t0 = d0 + bb.x, t1 = d1 + bb.y;
                float t2 = d2 + bb.x, t3 = d3 + bb.y;
                t0 = 0.5f * t0 * (1.f + erff(t0 * 0.70710678118654752f));
                t1 = 0.5f * t1 * (1.f + erff(t1 * 0.70710678118654752f));
                t2 = 0.5f * t2 * (1.f + erff(t2 * 0.70710678118654752f));
                t3 = 0.5f * t3 * (1.f + erff(t3 * 0.70710678118654752f));
                *(float2*)(C + (long)m * N + n)       = make_float2(t0, t1);
                *(float2*)(C + (long)(m + 8) * N + n) = make_float2(t2, t3);
            }
        }
    }
}

// ---------------------------------------------------------------------------
// Row softmax over L_=1024. One block (256 thr, 4 elems/thr) per row.
// ---------------------------------------------------------------------------
__global__ void __launch_bounds__(256)
softmax_k(float* __restrict__ S)
{
    const long row = blockIdx.x;
    float* p = S + row * (long)L_;
    const int tid = threadIdx.x;
    __shared__ float red[8];

    float4 x = *(float4*)(p + (tid << 2));

    float mx = fmaxf(fmaxf(x.x, x.y), fmaxf(x.z, x.w));
#pragma unroll
    for (int o = 16; o; o >>= 1) mx = fmaxf(mx, __shfl_xor_sync(0xffffffffu, mx, o));
    if ((tid & 31) == 0) red[tid >> 5] = mx;
    __syncthreads();
    if (tid == 0) {
        float t = red[0];
#pragma unroll
        for (int i = 1; i < 8; i++) t = fmaxf(t, red[i]);
        red[0] = t;
    }
    __syncthreads();
    mx = red[0];
    __syncthreads();

    float e0 = __expf(x.x - mx), e1 = __expf(x.y - mx);
    float e2 = __expf(x.z - mx), e3 = __expf(x.w - mx);
    float s = e0 + e1 + e2 + e3;
#pragma unroll
    for (int o = 16; o; o >>= 1) s += __shfl_xor_sync(0xffffffffu, s, o);
    if ((tid & 31) == 0) red[tid >> 5] = s;
    __syncthreads();
    if (tid == 0) {
        float t = 0.f;
#pragma unroll
        for (int i = 1; i < 8; i++) t += red[i];
        red[0] += t;
    }
    __syncthreads();
    const float inv = 1.0f / red[0];

    *(float4*)(p + (tid << 2)) = make_float4(e0 * inv, e1 * inv, e2 * inv, e3 * inv);
}

// ---------------------------------------------------------------------------
// Fused moving_avg (window 25, zero-pad 12) + LayerNorm. 16 rows / block.
// ---------------------------------------------------------------------------
__global__ void __launch_bounds__(256)
mvln_k(const float* __restrict__ X, float* __restrict__ Y,
       const float* __restrict__ g, const float* __restrict__ b)
{
    __shared__ float tr[16][D_];
    const int bidx = blockIdx.x;
    const int bb = bidx >> 6;
    const int l0 = (bidx & 63) * 16;
    const float* Xb = X + (long)bb * L_ * D_;
    const int tid = threadIdx.x;

    for (int task = tid; task < 16 * 128; task += 256) {
        const int r  = task >> 7;
        const int dg = task & 127;
        const int l  = l0 + r;
        float4 s = make_float4(0.f, 0.f, 0.f, 0.f);
        const int j0 = l - 12;
#pragma unroll
        for (int j = 0; j < 25; j++) {
            const int ll = j0 + j;
            if (ll >= 0 && ll < L_) {
                float4 xv = *(const float4*)(Xb + (long)ll * D_ + (dg << 2));
                s.x += xv.x; s.y += xv.y; s.z += xv.z; s.w += xv.w;
            }
        }
        const float inv = 1.f / 25.f;
        *(float4*)&tr[r][dg << 2] = make_float4(s.x * inv, s.y * inv, s.z * inv, s.w * inv);
    }
    __syncthreads();

    const int wid = tid >> 5, lane = tid & 31;
#pragma unroll
    for (int rr = 0; rr < 2; rr++) {
        const int r = wid * 2 + rr;
        float sum = 0.f, sq = 0.f;
        for (int d = lane; d < D_; d += 32) {
            float v = tr[r][d];
            sum += v; sq += v * v;
        }
#pragma unroll
        for (int o = 16; o; o >>= 1) {
            sum += __shfl_xor_sync(0xffffffffu, sum, o);
            sq  += __shfl_xor_sync(0xffffffffu, sq, o);
        }
        const float mu   = sum * (1.f / D_);
        const float var  = sq * (1.f / D_) - mu * mu;
        const float rstd = rsqrtf(var + 1e-5f);
        float* Yo = Y + ((long)bb * L_ + l0 + r) * D_;
        for (int d = lane; d < D_; d += 32)
            Yo[d] = (tr[r][d] - mu) * rstd * g[d] + b[d];
    }
}

// ---------------------------------------------------------------------------
extern "C" void kernel_launch(void* const* d_in, const int* in_sizes, int n_in,
                              void* d_out, int out_size)
{
    (void)in_sizes; (void)n_in; (void)out_size;
    const float* x     = (const float*)d_in[0];
    const float* enc   = (const float*)d_in[1];
    const float* sa_Wq = (const float*)d_in[2];  const float* sa_bq = (const float*)d_in[3];
    const float* sa_Wk = (const float*)d_in[4];  const float* sa_bk = (const float*)d_in[5];
    const float* sa_Wv = (const float*)d_in[6];  const float* sa_bv = (const float*)d_in[7];
    const float* sa_Wo = (const float*)d_in[8];  const float* sa_bo = (const float*)d_in[9];
    const float* ca_Wq = (const float*)d_in[10]; const float* ca_bq = (const float*)d_in[11];
    const float* ca_Wk = (const float*)d_in[12]; const float* ca_bk = (const float*)d_in[13];
    const float* ca_Wv = (const float*)d_in[14]; const float* ca_bv = (const float*)d_in[15];
    const float* ca_Wo = (const float*)d_in[16]; const float* ca_bo = (const float*)d_in[17];
    const float* ff_W1 = (const float*)d_in[18]; const float* ff_b1 = (const float*)d_in[19];
    const float* ff_W2 = (const float*)d_in[20]; const float* ff_b2 = (const float*)d_in[21];
    const float* n1_g  = (const float*)d_in[22]; const float* n1_b  = (const float*)d_in[23];
    const float* n2_g  = (const float*)d_in[24]; const float* n2_b  = (const float*)d_in[25];
    const float* n3_g  = (const float*)d_in[26]; const float* n3_b  = (const float*)d_in[27];
    float* out = (float*)d_out;

    float *q, *k, *vt, *S, *ctx, *bufA, *bufB, *ff;
    cudaGetSymbolAddress((void**)&q,    g_q);
    cudaGetSymbolAddress((void**)&k,    g_k);
    cudaGetSymbolAddress((void**)&vt,   g_vt);
    cudaGetSymbolAddress((void**)&S,    g_S);
    cudaGetSymbolAddress((void**)&ctx,  g_ctx);
    cudaGetSymbolAddress((void**)&bufA, g_bufA);
    cudaGetSymbolAddress((void**)&bufB, g_bufB);
    cudaGetSymbolAddress((void**)&ff,   g_ff);

    const dim3 thr(256);
    const dim3 gProj(D_ / 64, M_ / 128, 1);        // (8, 64)
    const dim3 gFF1(DFF_ / 64, M_ / 128, 1);       // (32, 64)
    const dim3 gScore(L_ / 64, L_ / 128, B_ * H_); // (16, 8, 64)
    const dim3 gPV(1, L_ / 128, B_ * H_);          // (1, 8, 64)
    const dim3 gSm(B_ * H_ * L_, 1, 1);
    const dim3 gMv(B_ * L_ / 16, 1, 1);

    // ===================== self-attention =====================
    gemm_tc<EP_QKV>   <<<gProj, thr>>>(x, sa_Wq, sa_bq, nullptr, q,  D_, D_, D_, D_, 0, 0);
    gemm_tc<EP_QKV>   <<<gProj, thr>>>(x, sa_Wk, sa_bk, nullptr, k,  D_, D_, D_, D_, 0, 0);
    gemm_tc<EP_QKV_VT><<<gProj, thr>>>(x, sa_Wv, sa_bv, nullptr, vt, D_, D_, D_, D_, 0, 0);
    gemm_tc<EP_SCORE> <<<gScore, thr>>>(q, k, nullptr, nullptr, S, L_, DK_, DK_, DK_,
                                        (long)L_ * DK_, (long)L_ * DK_);
    softmax_k<<<gSm, thr>>>(S);
    gemm_tc<EP_CTX>   <<<gPV, thr>>>(S, vt, nullptr, nullptr, ctx, DK_, L_, L_, L_,
                                     (long)L_ * L_, (long)DK_ * L_);
    gemm_tc<EP_BIAS_RES><<<gProj, thr>>>(ctx, sa_Wo, sa_bo, x, bufA, D_, D_, D_, D_, 0, 0);
    mvln_k<<<gMv, thr>>>(bufA, bufB, n1_g, n1_b);

    // ===================== cross-attention =====================
    gemm_tc<EP_QKV>   <<<gProj, thr>>>(bufB, ca_Wq, ca_bq, nullptr, q,  D_, D_, D_, D_, 0, 0);
    gemm_tc<EP_QKV>   <<<gProj, thr>>>(enc,  ca_Wk, ca_bk, nullptr, k,  D_, D_, D_, D_, 0, 0);
    gemm_tc<EP_QKV_VT><<<gProj, thr>>>(enc,  ca_Wv, ca_bv, nullptr, vt, D_, D_, D_, D_, 0, 0);
    gemm_tc<EP_SCORE> <<<gScore, thr>>>(q, k, nullptr, nullptr, S, L_, DK_, DK_, DK_,
                                        (long)L_ * DK_, (long)L_ * DK_);
    softmax_k<<<gSm, thr>>>(S);
    gemm_tc<EP_CTX>   <<<gPV, thr>>>(S, vt, nullptr, nullptr, ctx, DK_, L_, L_, L_,
                                     (long)L_ * L_, (long)DK_ * L_);
    gemm_tc<EP_BIAS_RES><<<gProj, thr>>>(ctx, ca_Wo, ca_bo, bufB, bufA, D_, D_, D_, D_, 0, 0);
    mvln_k<<<gMv, thr>>>(bufA, bufB, n2_g, n2_b);

    // ===================== feed-forward =====================
    gemm_tc<EP_GELU><<<gFF1, thr>>>(bufB, ff_W1, ff_b1, nullptr, ff, DFF_, D_, D_, D_, 0, 0);
    gemm_tc<EP_BIAS_RES><<<gProj, thr>>>(ff, ff_W2, ff_b2, bufB, bufA, D_, DFF_, DFF_, DFF_, 0, 0);
    mvln_k<<<gMv, thr>>>(bufA, out, n3_g, n3_b);
}

// round 3
// speedup vs baseline: 2.3331x; 1.1117x over previous
#include <cuda_runtime.h>
#include <math.h>
#include <stdint.h>

#define B_   8
#define L_   1024
#define D_   512
#define H_   8
#define DK_  64
#define DFF_ 2048
#define M_   (B_*L_)

// ---------------- device scratch (static: no runtime allocation) ----------------
__device__ float g_q  [B_*H_*L_*DK_];            // (B,H,L,DK)
__device__ float g_k  [B_*H_*L_*DK_];
__device__ float g_vt [B_*H_*DK_*L_];            // (B,H,DK,L)  V transposed
__device__ float g_S  [(size_t)B_*H_*L_*L_];     // (B,H,L,L) scores / probs
__device__ float g_ctx[M_*D_];
__device__ float g_bufA[M_*D_];
__device__ float g_bufB[M_*D_];
__device__ float g_ff [M_*DFF_];

// ---------------- epilogue modes ----------------
enum {
    EP_QKV = 0,      // +bias, permuted write to (B,H,L,DK)
    EP_QKV_VT = 1,   // +bias, transposed write to (B,H,DK,L)
    EP_SCORE = 2,    // acc*0.125 - 0.1*|m-n| -> S[z]
    EP_CTX = 3,      // batched write to (B,L,D) context
    EP_BIAS_RES = 4, // +bias +res
    EP_GELU = 5      // gelu(acc+bias), exact erf
};

// ---------------- PTX helpers ----------------
__device__ __forceinline__ void mma8(float* d, const uint32_t* a, const uint32_t* b) {
    asm volatile(
        "mma.sync.aligned.m16n8k8.row.col.f32.tf32.tf32.f32 "
        "{%0,%1,%2,%3}, {%4,%5,%6,%7}, {%8,%9}, {%0,%1,%2,%3};"
        : "+f"(d[0]), "+f"(d[1]), "+f"(d[2]), "+f"(d[3])
        : "r"(a[0]), "r"(a[1]), "r"(a[2]), "r"(a[3]), "r"(b[0]), "r"(b[1]));
}
__device__ __forceinline__ void cpa16(uint32_t dst, const float* src) {
    asm volatile("cp.async.ca.shared.global [%0], [%1], 16;" :: "r"(dst), "l"(src));
}
#define CP_COMMIT() asm volatile("cp.async.commit_group;")
#define CP_WAIT(n)  asm volatile("cp.async.wait_group %0;" :: "n"(n))

// ---------------------------------------------------------------------------
// tf32 tensor-core GEMM: C = A * B^T
//   A: M x K row-major (lda). B: N x K row-major (ldb). All tiles exact.
// Tile BM=128, BN(template)=64|128, BK=16. 256 thr = 8 warps (4m x 2n).
// Warp tile 32 x (BN/2). Raw f32 bits fed to tf32 MMA (hardware truncation,
// no cvt instructions). cp.async double-buffered, stride-20 padded smem.
// ---------------------------------------------------------------------------
template<int EP, int BN>
__global__ void __launch_bounds__(256)
gemm_tc(const float* __restrict__ A, const float* __restrict__ Bm,
        const float* __restrict__ bias, const float* __restrict__ res,
        float* __restrict__ C,
        int N, int K, int lda, int ldb,
        long sAb, long sBb)
{
    constexpr int NI = BN / 16;      // n-tiles of 8 per warp (4 or 8)
    __shared__ float As[2][128][20];
    __shared__ float Bs[2][BN][20];

    const int z  = blockIdx.z;
    const float* Ab = A  + (long)z * sAb;
    const float* Bb = Bm + (long)z * sBb;
    const int by = blockIdx.y, bx = blockIdx.x;
    const int tid  = threadIdx.x;
    const int lane = tid & 31;
    const int warp = tid >> 5;
    const int wm = warp & 3;        // 0..3
    const int wn = warp >> 2;       // 0..1

    const uint32_t sA = (uint32_t)__cvta_generic_to_shared(&As[0][0][0]);
    const uint32_t sB = (uint32_t)__cvta_generic_to_shared(&Bs[0][0][0]);

    float acc[2][NI][4];
#pragma unroll
    for (int mi = 0; mi < 2; mi++)
#pragma unroll
        for (int ni = 0; ni < NI; ni++)
#pragma unroll
            for (int r = 0; r < 4; r++) acc[mi][ni][r] = 0.f;

    const int arow0 = tid >> 2;           // 0..63
    const int akq   = (tid & 3) << 2;

    const int nT = K >> 4;

    // ---- prologue: stage 0 ----
    {
#pragma unroll
        for (int e = 0; e < 2; e++) {
            int row = arow0 + e * 64;
            cpa16(sA + (uint32_t)((row * 20 + akq) * 4),
                  Ab + (long)(by * 128 + row) * lda + akq);
        }
#pragma unroll
        for (int e = 0; e < BN / 64; e++) {
            int row = arow0 + e * 64;
            cpa16(sB + (uint32_t)((row * 20 + akq) * 4),
                  Bb + (long)(bx * BN + row) * ldb + akq);
        }
        CP_COMMIT();
    }

    for (int kt = 0; kt < nT; kt++) {
        const int st = kt & 1;
        if (kt + 1 < nT) {
            const int ns = st ^ 1;
            const int k0 = (kt + 1) << 4;
#pragma unroll
            for (int e = 0; e < 2; e++) {
                int row = arow0 + e * 64;
                cpa16(sA + (uint32_t)(((ns * 128 + row) * 20 + akq) * 4),
                      Ab + (long)(by * 128 + row) * lda + k0 + akq);
            }
#pragma unroll
            for (int e = 0; e < BN / 64; e++) {
                int row = arow0 + e * 64;
                cpa16(sB + (uint32_t)(((ns * BN + row) * 20 + akq) * 4),
                      Bb + (long)(bx * BN + row) * ldb + k0 + akq);
            }
            CP_COMMIT();
            CP_WAIT(1);
        } else {
            CP_WAIT(0);
        }
        __syncthreads();

        // ---- compute this stage: 2 k8-steps (raw f32 bits -> tf32 MMA) ----
#pragma unroll
        for (int ks = 0; ks < 2; ks++) {
            const int kc = (ks << 3) + (lane & 3);
            uint32_t afr[2][4], bfr[NI][2];
#pragma unroll
            for (int mi = 0; mi < 2; mi++) {
                const int r = wm * 32 + mi * 16 + (lane >> 2);
                afr[mi][0] = __float_as_uint(As[st][r][kc]);
                afr[mi][1] = __float_as_uint(As[st][r + 8][kc]);
                afr[mi][2] = __float_as_uint(As[st][r][kc + 4]);
                afr[mi][3] = __float_as_uint(As[st][r + 8][kc + 4]);
            }
#pragma unroll
            for (int ni = 0; ni < NI; ni++) {
                const int r = wn * (BN / 2) + ni * 8 + (lane >> 2);
                bfr[ni][0] = __float_as_uint(Bs[st][r][kc]);
                bfr[ni][1] = __float_as_uint(Bs[st][r][kc + 4]);
            }
#pragma unroll
            for (int mi = 0; mi < 2; mi++)
#pragma unroll
                for (int ni = 0; ni < NI; ni++)
                    mma8(acc[mi][ni], afr[mi], bfr[ni]);
        }
        __syncthreads();
    }

    // ---- epilogue ----
#pragma unroll
    for (int mi = 0; mi < 2; mi++) {
#pragma unroll
        for (int ni = 0; ni < NI; ni++) {
            const int m = by * 128 + wm * 32 + mi * 16 + (lane >> 2);
            const int n = bx * BN + wn * (BN / 2) + ni * 8 + ((lane & 3) << 1);
            float d0 = acc[mi][ni][0], d1 = acc[mi][ni][1];
            float d2 = acc[mi][ni][2], d3 = acc[mi][ni][3];

            if (EP == EP_SCORE) {
                float* Cz = C + (long)z * L_ * L_;
                float v0 = d0 * 0.125f - 0.1f * fabsf((float)(m - n));
                float v1 = d1 * 0.125f - 0.1f * fabsf((float)(m - n - 1));
                float v2 = d2 * 0.125f - 0.1f * fabsf((float)(m + 8 - n));
                float v3 = d3 * 0.125f - 0.1f * fabsf((float)(m + 8 - n - 1));
                *(float2*)(Cz + (long)m * L_ + n)       = make_float2(v0, v1);
                *(float2*)(Cz + (long)(m + 8) * L_ + n) = make_float2(v2, v3);
            } else if (EP == EP_QKV) {
                float2 bb = *(const float2*)(bias + n);
                const int h = n >> 6, dk = n & 63;
                {
                    int b = m >> 10, l = m & 1023;
                    *(float2*)(C + ((long)(b * H_ + h) * L_ + l) * DK_ + dk) =
                        make_float2(d0 + bb.x, d1 + bb.y);
                }
                {
                    int mm = m + 8;
                    int b = mm >> 10, l = mm & 1023;
                    *(float2*)(C + ((long)(b * H_ + h) * L_ + l) * DK_ + dk) =
                        make_float2(d2 + bb.x, d3 + bb.y);
                }
            } else if (EP == EP_QKV_VT) {
                float2 bb = *(const float2*)(bias + n);
                const int h = n >> 6, dk = n & 63;
                {
                    int b = m >> 10, l = m & 1023;
                    long base = ((long)(b * H_ + h) * DK_ + dk) * L_ + l;
                    C[base]      = d0 + bb.x;
                    C[base + L_] = d1 + bb.y;
                }
                {
                    int mm = m + 8;
                    int b = mm >> 10, l = mm & 1023;
                    long base = ((long)(b * H_ + h) * DK_ + dk) * L_ + l;
                    C[base]      = d2 + bb.x;
                    C[base + L_] = d3 + bb.y;
                }
            } else if (EP == EP_CTX) {
                const int b = z >> 3, h = z & 7;
                *(float2*)(C + ((long)b * L_ + m) * D_ + h * DK_ + n) =
                    make_float2(d0, d1);
                *(float2*)(C + ((long)b * L_ + m + 8) * D_ + h * DK_ + n) =
                    make_float2(d2, d3);
            } else if (EP == EP_BIAS_RES) {
                float2 bb = *(const float2*)(bias + n);
                float2 r0 = *(const float2*)(res + (long)m * N + n);
                float2 r1 = *(const float2*)(res + (long)(m + 8) * N + n);
                *(float2*)(C + (long)m * N + n) =
                    make_float2(d0 + bb.x + r0.x, d1 + bb.y + r0.y);
                *(float2*)(C + (long)(m + 8) * N + n) =
                    make_float2(d2 + bb.x + r1.x, d3 + bb.y + r1.y);
            } else if (EP == EP_GELU) {
                float2 bb = *(const float2*)(bias + n);
                float t0 = d0 + bb.x, t1 = d1 + bb.y;
                float t2 = d2 + bb.x, t3 = d3 + bb.y;
                t0 = 0.5f * t0 * (1.f + erff(t0 * 0.70710678118654752f));
                t1 = 0.5f * t1 * (1.f + erff(t1 * 0.70710678118654752f));
                t2 = 0.5f * t2 * (1.f + erff(t2 * 0.70710678118654752f));
                t3 = 0.5f * t3 * (1.f + erff(t3 * 0.70710678118654752f));
                *(float2*)(C + (long)m * N + n)       = make_float2(t0, t1);
                *(float2*)(C + (long)(m + 8) * N + n) = make_float2(t2, t3);
            }
        }
    }
}

// ---------------------------------------------------------------------------
// Row softmax over L_=1024. One block (256 thr, 4 elems/thr) per row.
// ---------------------------------------------------------------------------
__global__ void __launch_bounds__(256)
softmax_k(float* __restrict__ S)
{
    const long row = blockIdx.x;
    float* p = S + row * (long)L_;
    const int tid = threadIdx.x;
    __shared__ float red[8];

    float4 x = *(float4*)(p + (tid << 2));

    float mx = fmaxf(fmaxf(x.x, x.y), fmaxf(x.z, x.w));
#pragma unroll
    for (int o = 16; o; o >>= 1) mx = fmaxf(mx, __shfl_xor_sync(0xffffffffu, mx, o));
    if ((tid & 31) == 0) red[tid >> 5] = mx;
    __syncthreads();
    if (tid == 0) {
        float t = red[0];
#pragma unroll
        for (int i = 1; i < 8; i++) t = fmaxf(t, red[i]);
        red[0] = t;
    }
    __syncthreads();
    mx = red[0];
    __syncthreads();

    float e0 = __expf(x.x - mx), e1 = __expf(x.y - mx);
    float e2 = __expf(x.z - mx), e3 = __expf(x.w - mx);
    float s = e0 + e1 + e2 + e3;
#pragma unroll
    for (int o = 16; o; o >>= 1) s += __shfl_xor_sync(0xffffffffu, s, o);
    if ((tid & 31) == 0) red[tid >> 5] = s;
    __syncthreads();
    if (tid == 0) {
        float t = 0.f;
#pragma unroll
        for (int i = 1; i < 8; i++) t += red[i];
        red[0] += t;
    }
    __syncthreads();
    const float inv = 1.0f / red[0];

    *(float4*)(p + (tid << 2)) = make_float4(e0 * inv, e1 * inv, e2 * inv, e3 * inv);
}

// ---------------------------------------------------------------------------
// Fused moving_avg (window 25, zero-pad 12) + LayerNorm. 16 rows / block.
// ---------------------------------------------------------------------------
__global__ void __launch_bounds__(256)
mvln_k(const float* __restrict__ X, float* __restrict__ Y,
       const float* __restrict__ g, const float* __restrict__ b)
{
    __shared__ float tr[16][D_];
    const int bidx = blockIdx.x;
    const int bb = bidx >> 6;
    const int l0 = (bidx & 63) * 16;
    const float* Xb = X + (long)bb * L_ * D_;
    const int tid = threadIdx.x;

    for (int task = tid; task < 16 * 128; task += 256) {
        const int r  = task >> 7;
        const int dg = task & 127;
        const int l  = l0 + r;
        float4 s = make_float4(0.f, 0.f, 0.f, 0.f);
        const int j0 = l - 12;
#pragma unroll
        for (int j = 0; j < 25; j++) {
            const int ll = j0 + j;
            if (ll >= 0 && ll < L_) {
                float4 xv = *(const float4*)(Xb + (long)ll * D_ + (dg << 2));
                s.x += xv.x; s.y += xv.y; s.z += xv.z; s.w += xv.w;
            }
        }
        const float inv = 1.f / 25.f;
        *(float4*)&tr[r][dg << 2] = make_float4(s.x * inv, s.y * inv, s.z * inv, s.w * inv);
    }
    __syncthreads();

    const int wid = tid >> 5, lane = tid & 31;
#pragma unroll
    for (int rr = 0; rr < 2; rr++) {
        const int r = wid * 2 + rr;
        float sum = 0.f, sq = 0.f;
        for (int d = lane; d < D_; d += 32) {
            float v = tr[r][d];
            sum += v; sq += v * v;
        }
#pragma unroll
        for (int o = 16; o; o >>= 1) {
            sum += __shfl_xor_sync(0xffffffffu, sum, o);
            sq  += __shfl_xor_sync(0xffffffffu, sq, o);
        }
        const float mu   = sum * (1.f / D_);
        const float var  = sq * (1.f / D_) - mu * mu;
        const float rstd = rsqrtf(var + 1e-5f);
        float* Yo = Y + ((long)bb * L_ + l0 + r) * D_;
        for (int d = lane; d < D_; d += 32)
            Yo[d] = (tr[r][d] - mu) * rstd * g[d] + b[d];
    }
}

// ---------------------------------------------------------------------------
extern "C" void kernel_launch(void* const* d_in, const int* in_sizes, int n_in,
                              void* d_out, int out_size)
{
    (void)in_sizes; (void)n_in; (void)out_size;
    const float* x     = (const float*)d_in[0];
    const float* enc   = (const float*)d_in[1];
    const float* sa_Wq = (const float*)d_in[2];  const float* sa_bq = (const float*)d_in[3];
    const float* sa_Wk = (const float*)d_in[4];  const float* sa_bk = (const float*)d_in[5];
    const float* sa_Wv = (const float*)d_in[6];  const float* sa_bv = (const float*)d_in[7];
    const float* sa_Wo = (const float*)d_in[8];  const float* sa_bo = (const float*)d_in[9];
    const float* ca_Wq = (const float*)d_in[10]; const float* ca_bq = (const float*)d_in[11];
    const float* ca_Wk = (const float*)d_in[12]; const float* ca_bk = (const float*)d_in[13];
    const float* ca_Wv = (const float*)d_in[14]; const float* ca_bv = (const float*)d_in[15];
    const float* ca_Wo = (const float*)d_in[16]; const float* ca_bo = (const float*)d_in[17];
    const float* ff_W1 = (const float*)d_in[18]; const float* ff_b1 = (const float*)d_in[19];
    const float* ff_W2 = (const float*)d_in[20]; const float* ff_b2 = (const float*)d_in[21];
    const float* n1_g  = (const float*)d_in[22]; const float* n1_b  = (const float*)d_in[23];
    const float* n2_g  = (const float*)d_in[24]; const float* n2_b  = (const float*)d_in[25];
    const float* n3_g  = (const float*)d_in[26]; const float* n3_b  = (const float*)d_in[27];
    float* out = (float*)d_out;

    float *q, *k, *vt, *S, *ctx, *bufA, *bufB, *ff;
    cudaGetSymbolAddress((void**)&q,    g_q);
    cudaGetSymbolAddress((void**)&k,    g_k);
    cudaGetSymbolAddress((void**)&vt,   g_vt);
    cudaGetSymbolAddress((void**)&S,    g_S);
    cudaGetSymbolAddress((void**)&ctx,  g_ctx);
    cudaGetSymbolAddress((void**)&bufA, g_bufA);
    cudaGetSymbolAddress((void**)&bufB, g_bufB);
    cudaGetSymbolAddress((void**)&ff,   g_ff);

    const dim3 thr(256);
    const dim3 gProj(D_ / 128, M_ / 128, 1);        // (4, 64)
    const dim3 gFF1(DFF_ / 128, M_ / 128, 1);       // (16, 64)
    const dim3 gScore(L_ / 128, L_ / 128, B_ * H_); // (8, 8, 64)
    const dim3 gPV(1, L_ / 128, B_ * H_);           // (1, 8, 64)  BN=64
    const dim3 gSm(B_ * H_ * L_, 1, 1);
    const dim3 gMv(B_ * L_ / 16, 1, 1);

    // ===================== self-attention =====================
    gemm_tc<EP_QKV, 128>   <<<gProj, thr>>>(x, sa_Wq, sa_bq, nullptr, q,  D_, D_, D_, D_, 0, 0);
    gemm_tc<EP_QKV, 128>   <<<gProj, thr>>>(x, sa_Wk, sa_bk, nullptr, k,  D_, D_, D_, D_, 0, 0);
    gemm_tc<EP_QKV_VT, 128><<<gProj, thr>>>(x, sa_Wv, sa_bv, nullptr, vt, D_, D_, D_, D_, 0, 0);
    gemm_tc<EP_SCORE, 128> <<<gScore, thr>>>(q, k, nullptr, nullptr, S, L_, DK_, DK_, DK_,
                                             (long)L_ * DK_, (long)L_ * DK_);
    softmax_k<<<gSm, thr>>>(S);
    gemm_tc<EP_CTX, 64>    <<<gPV, thr>>>(S, vt, nullptr, nullptr, ctx, DK_, L_, L_, L_,
                                          (long)L_ * L_, (long)DK_ * L_);
    gemm_tc<EP_BIAS_RES, 128><<<gProj, thr>>>(ctx, sa_Wo, sa_bo, x, bufA, D_, D_, D_, D_, 0, 0);
    mvln_k<<<gMv, thr>>>(bufA, bufB, n1_g, n1_b);

    // ===================== cross-attention =====================
    gemm_tc<EP_QKV, 128>   <<<gProj, thr>>>(bufB, ca_Wq, ca_bq, nullptr, q,  D_, D_, D_, D_, 0, 0);
    gemm_tc<EP_QKV, 128>   <<<gProj, thr>>>(enc,  ca_Wk, ca_bk, nullptr, k,  D_, D_, D_, D_, 0, 0);
    gemm_tc<EP_QKV_VT, 128><<<gProj, thr>>>(enc,  ca_Wv, ca_bv, nullptr, vt, D_, D_, D_, D_, 0, 0);
    gemm_tc<EP_SCORE, 128> <<<gScore, thr>>>(q, k, nullptr, nullptr, S, L_, DK_, DK_, DK_,
                                             (long)L_ * DK_, (long)L_ * DK_);
    softmax_k<<<gSm, thr>>>(S);
    gemm_tc<EP_CTX, 64>    <<<gPV, thr>>>(S, vt, nullptr, nullptr, ctx, DK_, L_, L_, L_,
                                          (long)L_ * L_, (long)DK_ * L_);
    gemm_tc<EP_BIAS_RES, 128><<<gProj, thr>>>(ctx, ca_Wo, ca_bo, bufB, bufA, D_, D_, D_, D_, 0, 0);
    mvln_k<<<gMv, thr>>>(bufA, bufB, n2_g, n2_b);

    // ===================== feed-forward =====================
    gemm_tc<EP_GELU, 128><<<gFF1, thr>>>(bufB, ff_W1, ff_b1, nullptr, ff, DFF_, D_, D_, D_, 0, 0);
    gemm_tc<EP_BIAS_RES, 128><<<gProj, thr>>>(ff, ff_W2, ff_b2, bufB, bufA, D_, DFF_, DFF_, DFF_, 0, 0);
    mvln_k<<<gMv, thr>>>(bufA, out, n3_g, n3_b);
}

// round 5
// speedup vs baseline: 2.6295x; 1.1270x over previous
#include <cuda_runtime.h>
#include <math.h>
#include <stdint.h>

#define B_   8
#define L_   1024
#define D_   512
#define H_   8
#define DK_  64
#define DFF_ 2048
#define M_   (B_*L_)

// ---------------- device scratch (static: no runtime allocation) ----------------
__device__ float g_q  [B_*H_*L_*DK_];            // (B,H,L,DK)
__device__ float g_k  [B_*H_*L_*DK_];
__device__ float g_v  [B_*H_*L_*DK_];
__device__ float g_ctx[M_*D_];
__device__ float g_bufA[M_*D_];
__device__ float g_bufB[M_*D_];
__device__ float g_ff [M_*DFF_];

// ---------------- epilogue modes ----------------
enum {
    EP_QKV = 0,      // +bias, permuted write to (B,H,L,DK)
    EP_BIAS_RES = 1, // +bias +res
    EP_GELU = 2      // gelu(acc+bias), exact erf
};

// ---------------- PTX helpers ----------------
__device__ __forceinline__ uint32_t f2tf(float f) {
    uint32_t u;
    asm("cvt.rna.tf32.f32 %0, %1;" : "=r"(u) : "f"(f));
    return u;
}
__device__ __forceinline__ void mma8(float* d, const uint32_t* a, const uint32_t* b) {
    asm volatile(
        "mma.sync.aligned.m16n8k8.row.col.f32.tf32.tf32.f32 "
        "{%0,%1,%2,%3}, {%4,%5,%6,%7}, {%8,%9}, {%0,%1,%2,%3};"
        : "+f"(d[0]), "+f"(d[1]), "+f"(d[2]), "+f"(d[3])
        : "r"(a[0]), "r"(a[1]), "r"(a[2]), "r"(a[3]), "r"(b[0]), "r"(b[1]));
}
__device__ __forceinline__ void cpa16(uint32_t dst, const float* src) {
    asm volatile("cp.async.ca.shared.global [%0], [%1], 16;" :: "r"(dst), "l"(src));
}
#define CP_COMMIT() asm volatile("cp.async.commit_group;")
#define CP_WAIT(n)  asm volatile("cp.async.wait_group %0;" :: "n"(n))

// ---------------------------------------------------------------------------
// tf32 tensor-core GEMM: C = A * B^T (projections / FF only).
// Tile BM=128, BN=128, BK=16. 256 thr = 8 warps (4m x 2n), warp tile 32x64.
// rna-rounded tf32. cp.async double-buffered, stride-20 padded smem.
// ---------------------------------------------------------------------------
template<int EP, int BN>
__global__ void __launch_bounds__(256)
gemm_tc(const float* __restrict__ A, const float* __restrict__ Bm,
        const float* __restrict__ bias, const float* __restrict__ res,
        float* __restrict__ C,
        int N, int K, int lda, int ldb)
{
    constexpr int NI = BN / 16;
    __shared__ float As[2][128][20];
    __shared__ float Bs[2][BN][20];

    const int by = blockIdx.y, bx = blockIdx.x;
    const int tid  = threadIdx.x;
    const int lane = tid & 31;
    const int warp = tid >> 5;
    const int wm = warp & 3;
    const int wn = warp >> 2;

    const uint32_t sA = (uint32_t)__cvta_generic_to_shared(&As[0][0][0]);
    const uint32_t sB = (uint32_t)__cvta_generic_to_shared(&Bs[0][0][0]);

    float acc[2][NI][4];
#pragma unroll
    for (int mi = 0; mi < 2; mi++)
#pragma unroll
        for (int ni = 0; ni < NI; ni++)
#pragma unroll
            for (int r = 0; r < 4; r++) acc[mi][ni][r] = 0.f;

    const int arow0 = tid >> 2;
    const int akq   = (tid & 3) << 2;
    const int nT = K >> 4;

    {
#pragma unroll
        for (int e = 0; e < 2; e++) {
            int row = arow0 + e * 64;
            cpa16(sA + (uint32_t)((row * 20 + akq) * 4),
                  A + (long)(by * 128 + row) * lda + akq);
        }
#pragma unroll
        for (int e = 0; e < BN / 64; e++) {
            int row = arow0 + e * 64;
            cpa16(sB + (uint32_t)((row * 20 + akq) * 4),
                  Bm + (long)(bx * BN + row) * ldb + akq);
        }
        CP_COMMIT();
    }

    for (int kt = 0; kt < nT; kt++) {
        const int st = kt & 1;
        if (kt + 1 < nT) {
            const int ns = st ^ 1;
            const int k0 = (kt + 1) << 4;
#pragma unroll
            for (int e = 0; e < 2; e++) {
                int row = arow0 + e * 64;
                cpa16(sA + (uint32_t)(((ns * 128 + row) * 20 + akq) * 4),
                      A + (long)(by * 128 + row) * lda + k0 + akq);
            }
#pragma unroll
            for (int e = 0; e < BN / 64; e++) {
                int row = arow0 + e * 64;
                cpa16(sB + (uint32_t)(((ns * BN + row) * 20 + akq) * 4),
                      Bm + (long)(bx * BN + row) * ldb + k0 + akq);
            }
            CP_COMMIT();
            CP_WAIT(1);
        } else {
            CP_WAIT(0);
        }
        __syncthreads();

#pragma unroll
        for (int ks = 0; ks < 2; ks++) {
            const int kc = (ks << 3) + (lane & 3);
            uint32_t afr[2][4], bfr[NI][2];
#pragma unroll
            for (int mi = 0; mi < 2; mi++) {
                const int r = wm * 32 + mi * 16 + (lane >> 2);
                afr[mi][0] = f2tf(As[st][r][kc]);
                afr[mi][1] = f2tf(As[st][r + 8][kc]);
                afr[mi][2] = f2tf(As[st][r][kc + 4]);
                afr[mi][3] = f2tf(As[st][r + 8][kc + 4]);
            }
#pragma unroll
            for (int ni = 0; ni < NI; ni++) {
                const int r = wn * (BN / 2) + ni * 8 + (lane >> 2);
                bfr[ni][0] = f2tf(Bs[st][r][kc]);
                bfr[ni][1] = f2tf(Bs[st][r][kc + 4]);
            }
#pragma unroll
            for (int mi = 0; mi < 2; mi++)
#pragma unroll
                for (int ni = 0; ni < NI; ni++)
                    mma8(acc[mi][ni], afr[mi], bfr[ni]);
        }
        __syncthreads();
    }

#pragma unroll
    for (int mi = 0; mi < 2; mi++) {
#pragma unroll
        for (int ni = 0; ni < NI; ni++) {
            const int m = by * 128 + wm * 32 + mi * 16 + (lane >> 2);
            const int n = bx * BN + wn * (BN / 2) + ni * 8 + ((lane & 3) << 1);
            float d0 = acc[mi][ni][0], d1 = acc[mi][ni][1];
            float d2 = acc[mi][ni][2], d3 = acc[mi][ni][3];

            if (EP == EP_QKV) {
                float2 bb = *(const float2*)(bias + n);
                const int h = n >> 6, dk = n & 63;
                {
                    int b = m >> 10, l = m & 1023;
                    *(float2*)(C + ((long)(b * H_ + h) * L_ + l) * DK_ + dk) =
                        make_float2(d0 + bb.x, d1 + bb.y);
                }
                {
                    int mm = m + 8;
                    int b = mm >> 10, l = mm & 1023;
                    *(float2*)(C + ((long)(b * H_ + h) * L_ + l) * DK_ + dk) =
                        make_float2(d2 + bb.x, d3 + bb.y);
                }
            } else if (EP == EP_BIAS_RES) {
                float2 bb = *(const float2*)(bias + n);
                float2 r0 = *(const float2*)(res + (long)m * N + n);
                float2 r1 = *(const float2*)(res + (long)(m + 8) * N + n);
                *(float2*)(C + (long)m * N + n) =
                    make_float2(d0 + bb.x + r0.x, d1 + bb.y + r0.y);
                *(float2*)(C + (long)(m + 8) * N + n) =
                    make_float2(d2 + bb.x + r1.x, d3 + bb.y + r1.y);
            } else if (EP == EP_GELU) {
                float2 bb = *(const float2*)(bias + n);
                float t0 = d0 + bb.x, t1 = d1 + bb.y;
                float t2 = d2 + bb.x, t3 = d3 + bb.y;
                t0 = 0.5f * t0 * (1.f + erff(t0 * 0.70710678118654752f));
                t1 = 0.5f * t1 * (1.f + erff(t1 * 0.70710678118654752f));
                t2 = 0.5f * t2 * (1.f + erff(t2 * 0.70710678118654752f));
                t3 = 0.5f * t3 * (1.f + erff(t3 * 0.70710678118654752f));
                *(float2*)(C + (long)m * N + n)       = make_float2(t0, t1);
                *(float2*)(C + (long)(m + 8) * N + n) = make_float2(t2, t3);
            }
        }
    }
}

// ---------------------------------------------------------------------------
// Fused flash attention: softmax(Q K^T / 8 - 0.1|m-n|) V  -> ctx (B,L,D)
// Block: 128 queries of one (b,h). 256 thr / 8 warps, warp owns 16 q-rows.
// 16 chunks of 64 keys, K/V double-buffered via cp.async. P staged through
// warp-private smem to convert MMA C-frags to A-frags.
// Dynamic smem: Q 128x68 | K 2x64x68 | V 2x64x68 | P 8x16x68  (~136 KB)
// ---------------------------------------------------------------------------
#define QS_OFF 0
#define KS_OFF 8704
#define VS_OFF 17408
#define PS_OFF 26112
#define SMEM_FLASH_FLOATS 34816
#define SMEM_FLASH_BYTES  (SMEM_FLASH_FLOATS * 4)
#define KV_STG 4352        // floats per K/V stage (64*68)

__global__ void __launch_bounds__(256)
flash_k(const float* __restrict__ q, const float* __restrict__ k,
        const float* __restrict__ v, float* __restrict__ ctx)
{
    extern __shared__ float sm[];
    const uint32_t smB = (uint32_t)__cvta_generic_to_shared(sm);

    const int tid  = threadIdx.x;
    const int lane = tid & 31;
    const int w    = tid >> 5;
    const int r    = lane >> 2;     // 0..7
    const int qv   = lane & 3;      // 0..3
    const int q0   = blockIdx.x * 128;
    const int z    = blockIdx.y;    // b*H + h

    const float* kz = k + (long)z * L_ * DK_;
    const float* vz = v + (long)z * L_ * DK_;

    // ---- prologue: Q tile + chunk 0 of K/V ----
    {
        const float* Qg = q + ((long)z * L_ + q0) * DK_;
#pragma unroll
        for (int e = 0; e < 8; e++) {
            int idx = tid + e * 256;
            int row = idx >> 4, c4 = (idx & 15) << 2;
            cpa16(smB + (uint32_t)((QS_OFF + row * 68 + c4) << 2),
                  Qg + (long)row * DK_ + c4);
        }
#pragma unroll
        for (int e = 0; e < 4; e++) {
            int idx = tid + e * 256;
            int row = idx >> 4, c4 = (idx & 15) << 2;
            cpa16(smB + (uint32_t)((KS_OFF + row * 68 + c4) << 2),
                  kz + (long)row * DK_ + c4);
            cpa16(smB + (uint32_t)((VS_OFF + row * 68 + c4) << 2),
                  vz + (long)row * DK_ + c4);
        }
        CP_COMMIT();
    }

    float o[8][4];
#pragma unroll
    for (int j = 0; j < 8; j++)
#pragma unroll
        for (int t = 0; t < 4; t++) o[j][t] = 0.f;
    float m0 = -1e30f, m1 = -1e30f, l0 = 0.f, l1 = 0.f;

    const int qrow = w * 16 + r;               // local q row (first of pair)
    const float mg0 = (float)(q0 + qrow);
    float* Pw = sm + PS_OFF + w * 16 * 68;

    for (int c = 0; c < 16; c++) {
        const int st = c & 1;
        if (c + 1 < 16) {
            const int ns = st ^ 1;
            const float* Kg = kz + (long)(c + 1) * 64 * DK_;
            const float* Vg = vz + (long)(c + 1) * 64 * DK_;
#pragma unroll
            for (int e = 0; e < 4; e++) {
                int idx = tid + e * 256;
                int row = idx >> 4, c4 = (idx & 15) << 2;
                cpa16(smB + (uint32_t)((KS_OFF + ns * KV_STG + row * 68 + c4) << 2),
                      Kg + (long)row * DK_ + c4);
                cpa16(smB + (uint32_t)((VS_OFF + ns * KV_STG + row * 68 + c4) << 2),
                      Vg + (long)row * DK_ + c4);
            }
            CP_COMMIT();
            CP_WAIT(1);
        } else {
            CP_WAIT(0);
        }
        __syncthreads();

        // ---- S = Q K^T over this 64-key chunk ----
        float s[8][4];
#pragma unroll
        for (int j = 0; j < 8; j++)
#pragma unroll
            for (int t = 0; t < 4; t++) s[j][t] = 0.f;

        const float* Ks = sm + KS_OFF + st * KV_STG;
        const float* Vs = sm + VS_OFF + st * KV_STG;
#pragma unroll
        for (int ks = 0; ks < 8; ks++) {
            const int kc = ks * 8 + qv;
            uint32_t qa[4];
            qa[0] = f2tf(sm[QS_OFF + qrow * 68 + kc]);
            qa[1] = f2tf(sm[QS_OFF + (qrow + 8) * 68 + kc]);
            qa[2] = f2tf(sm[QS_OFF + qrow * 68 + kc + 4]);
            qa[3] = f2tf(sm[QS_OFF + (qrow + 8) * 68 + kc + 4]);
#pragma unroll
            for (int j = 0; j < 8; j++) {
                const int krow = j * 8 + r;
                uint32_t kb[2];
                kb[0] = f2tf(Ks[krow * 68 + kc]);
                kb[1] = f2tf(Ks[krow * 68 + kc + 4]);
                mma8(s[j], qa, kb);
            }
        }

        // ---- scale + ALiBi bias ----
#pragma unroll
        for (int j = 0; j < 8; j++) {
            const float nb = (float)(c * 64 + j * 8 + 2 * qv);
            s[j][0] = s[j][0] * 0.125f - 0.1f * fabsf(mg0 - nb);
            s[j][1] = s[j][1] * 0.125f - 0.1f * fabsf(mg0 - nb - 1.f);
            s[j][2] = s[j][2] * 0.125f - 0.1f * fabsf(mg0 + 8.f - nb);
            s[j][3] = s[j][3] * 0.125f - 0.1f * fabsf(mg0 + 8.f - nb - 1.f);
        }

        // ---- online softmax update ----
        float mx0 = -1e30f, mx1 = -1e30f;
#pragma unroll
        for (int j = 0; j < 8; j++) {
            mx0 = fmaxf(mx0, fmaxf(s[j][0], s[j][1]));
            mx1 = fmaxf(mx1, fmaxf(s[j][2], s[j][3]));
        }
        mx0 = fmaxf(mx0, __shfl_xor_sync(0xffffffffu, mx0, 1));
        mx0 = fmaxf(mx0, __shfl_xor_sync(0xffffffffu, mx0, 2));
        mx1 = fmaxf(mx1, __shfl_xor_sync(0xffffffffu, mx1, 1));
        mx1 = fmaxf(mx1, __shfl_xor_sync(0xffffffffu, mx1, 2));

        const float nm0 = fmaxf(m0, mx0);
        const float nm1 = fmaxf(m1, mx1);
        const float sc0 = __expf(m0 - nm0);
        const float sc1 = __expf(m1 - nm1);
        m0 = nm0; m1 = nm1;

        float rs0 = 0.f, rs1 = 0.f;
#pragma unroll
        for (int j = 0; j < 8; j++) {
            s[j][0] = __expf(s[j][0] - m0);
            s[j][1] = __expf(s[j][1] - m0);
            s[j][2] = __expf(s[j][2] - m1);
            s[j][3] = __expf(s[j][3] - m1);
            rs0 += s[j][0] + s[j][1];
            rs1 += s[j][2] + s[j][3];
        }
        rs0 += __shfl_xor_sync(0xffffffffu, rs0, 1);
        rs0 += __shfl_xor_sync(0xffffffffu, rs0, 2);
        rs1 += __shfl_xor_sync(0xffffffffu, rs1, 1);
        rs1 += __shfl_xor_sync(0xffffffffu, rs1, 2);
        l0 = l0 * sc0 + rs0;
        l1 = l1 * sc1 + rs1;

#pragma unroll
        for (int j = 0; j < 8; j++) {
            o[j][0] *= sc0; o[j][1] *= sc0;
            o[j][2] *= sc1; o[j][3] *= sc1;
        }

        // ---- stage P (warp-private), then O += P V ----
#pragma unroll
        for (int j = 0; j < 8; j++) {
            *(float2*)&Pw[r * 68 + j * 8 + 2 * qv]       = make_float2(s[j][0], s[j][1]);
            *(float2*)&Pw[(r + 8) * 68 + j * 8 + 2 * qv] = make_float2(s[j][2], s[j][3]);
        }
        __syncwarp();

#pragma unroll
        for (int ks = 0; ks < 8; ks++) {
            const int kc = ks * 8 + qv;
            uint32_t pa[4];
            pa[0] = f2tf(Pw[r * 68 + kc]);
            pa[1] = f2tf(Pw[(r + 8) * 68 + kc]);
            pa[2] = f2tf(Pw[r * 68 + kc + 4]);
            pa[3] = f2tf(Pw[(r + 8) * 68 + kc + 4]);
#pragma unroll
            for (int j = 0; j < 8; j++) {
                uint32_t vb[2];
                vb[0] = f2tf(Vs[kc * 68 + j * 8 + r]);
                vb[1] = f2tf(Vs[(kc + 4) * 68 + j * 8 + r]);
                mma8(o[j], pa, vb);
            }
        }
        __syncthreads();
    }

    // ---- epilogue: O / l -> ctx (B,L,D) ----
    const float inv0 = 1.0f / l0;
    const float inv1 = 1.0f / l1;
    const int b = z >> 3, h = z & 7;
    const int mglob = q0 + qrow;
    float* C0 = ctx + ((long)b * L_ + mglob) * D_ + h * DK_;
    float* C1 = C0 + 8 * D_;
#pragma unroll
    for (int j = 0; j < 8; j++) {
        const int n = j * 8 + 2 * qv;
        *(float2*)(C0 + n) = make_float2(o[j][0] * inv0, o[j][1] * inv0);
        *(float2*)(C1 + n) = make_float2(o[j][2] * inv1, o[j][3] * inv1);
    }
}

// ---------------------------------------------------------------------------
// Fused moving_avg (window 25, zero-pad 12) + LayerNorm. 16 rows / block.
// ---------------------------------------------------------------------------
__global__ void __launch_bounds__(256)
mvln_k(const float* __restrict__ X, float* __restrict__ Y,
       const float* __restrict__ g, const float* __restrict__ b)
{
    __shared__ float tr[16][D_];
    const int bidx = blockIdx.x;
    const int bb = bidx >> 6;
    const int l0 = (bidx & 63) * 16;
    const float* Xb = X + (long)bb * L_ * D_;
    const int tid = threadIdx.x;

    for (int task = tid; task < 16 * 128; task += 256) {
        const int r  = task >> 7;
        const int dg = task & 127;
        const int l  = l0 + r;
        float4 s = make_float4(0.f, 0.f, 0.f, 0.f);
        const int j0 = l - 12;
#pragma unroll
        for (int j = 0; j < 25; j++) {
            const int ll = j0 + j;
            if (ll >= 0 && ll < L_) {
                float4 xv = *(const float4*)(Xb + (long)ll * D_ + (dg << 2));
                s.x += xv.x; s.y += xv.y; s.z += xv.z; s.w += xv.w;
            }
        }
        const float inv = 1.f / 25.f;
        *(float4*)&tr[r][dg << 2] = make_float4(s.x * inv, s.y * inv, s.z * inv, s.w * inv);
    }
    __syncthreads();

    const int wid = tid >> 5, lane = tid & 31;
#pragma unroll
    for (int rr = 0; rr < 2; rr++) {
        const int r = wid * 2 + rr;
        float sum = 0.f, sq = 0.f;
        for (int d = lane; d < D_; d += 32) {
            float v = tr[r][d];
            sum += v; sq += v * v;
        }
#pragma unroll
        for (int o = 16; o; o >>= 1) {
            sum += __shfl_xor_sync(0xffffffffu, sum, o);
            sq  += __shfl_xor_sync(0xffffffffu, sq, o);
        }
        const float mu   = sum * (1.f / D_);
        const float var  = sq * (1.f / D_) - mu * mu;
        const float rstd = rsqrtf(var + 1e-5f);
        float* Yo = Y + ((long)bb * L_ + l0 + r) * D_;
        for (int d = lane; d < D_; d += 32)
            Yo[d] = (tr[r][d] - mu) * rstd * g[d] + b[d];
    }
}

// ---------------------------------------------------------------------------
extern "C" void kernel_launch(void* const* d_in, const int* in_sizes, int n_in,
                              void* d_out, int out_size)
{
    (void)in_sizes; (void)n_in; (void)out_size;
    const float* x     = (const float*)d_in[0];
    const float* enc   = (const float*)d_in[1];
    const float* sa_Wq = (const float*)d_in[2];  const float* sa_bq = (const float*)d_in[3];
    const float* sa_Wk = (const float*)d_in[4];  const float* sa_bk = (const float*)d_in[5];
    const float* sa_Wv = (const float*)d_in[6];  const float* sa_bv = (const float*)d_in[7];
    const float* sa_Wo = (const float*)d_in[8];  const float* sa_bo = (const float*)d_in[9];
    const float* ca_Wq = (const float*)d_in[10]; const float* ca_bq = (const float*)d_in[11];
    const float* ca_Wk = (const float*)d_in[12]; const float* ca_bk = (const float*)d_in[13];
    const float* ca_Wv = (const float*)d_in[14]; const float* ca_bv = (const float*)d_in[15];
    const float* ca_Wo = (const float*)d_in[16]; const float* ca_bo = (const float*)d_in[17];
    const float* ff_W1 = (const float*)d_in[18]; const float* ff_b1 = (const float*)d_in[19];
    const float* ff_W2 = (const float*)d_in[20]; const float* ff_b2 = (const float*)d_in[21];
    const float* n1_g  = (const float*)d_in[22]; const float* n1_b  = (const float*)d_in[23];
    const float* n2_g  = (const float*)d_in[24]; const float* n2_b  = (const float*)d_in[25];
    const float* n3_g  = (const float*)d_in[26]; const float* n3_b  = (const float*)d_in[27];
    float* out = (float*)d_out;

    float *q, *k, *v, *ctx, *bufA, *bufB, *ff;
    cudaGetSymbolAddress((void**)&q,    g_q);
    cudaGetSymbolAddress((void**)&k,    g_k);
    cudaGetSymbolAddress((void**)&v,    g_v);
    cudaGetSymbolAddress((void**)&ctx,  g_ctx);
    cudaGetSymbolAddress((void**)&bufA, g_bufA);
    cudaGetSymbolAddress((void**)&bufB, g_bufB);
    cudaGetSymbolAddress((void**)&ff,   g_ff);

    cudaFuncSetAttribute(flash_k, cudaFuncAttributeMaxDynamicSharedMemorySize,
                         SMEM_FLASH_BYTES);

    const dim3 thr(256);
    const dim3 gProj(D_ / 128, M_ / 128, 1);     // (4, 64)
    const dim3 gFF1(DFF_ / 128, M_ / 128, 1);    // (16, 64)
    const dim3 gFl(L_ / 128, B_ * H_, 1);        // (8, 64)
    const dim3 gMv(B_ * L_ / 16, 1, 1);

    // ===================== self-attention =====================
    gemm_tc<EP_QKV, 128><<<gProj, thr>>>(x, sa_Wq, sa_bq, nullptr, q, D_, D_, D_, D_);
    gemm_tc<EP_QKV, 128><<<gProj, thr>>>(x, sa_Wk, sa_bk, nullptr, k, D_, D_, D_, D_);
    gemm_tc<EP_QKV, 128><<<gProj, thr>>>(x, sa_Wv, sa_bv, nullptr, v, D_, D_, D_, D_);
    flash_k<<<gFl, thr, SMEM_FLASH_BYTES>>>(q, k, v, ctx);
    gemm_tc<EP_BIAS_RES, 128><<<gProj, thr>>>(ctx, sa_Wo, sa_bo, x, bufA, D_, D_, D_, D_);
    mvln_k<<<gMv, thr>>>(bufA, bufB, n1_g, n1_b);

    // ===================== cross-attention =====================
    gemm_tc<EP_QKV, 128><<<gProj, thr>>>(bufB, ca_Wq, ca_bq, nullptr, q, D_, D_, D_, D_);
    gemm_tc<EP_QKV, 128><<<gProj, thr>>>(enc,  ca_Wk, ca_bk, nullptr, k, D_, D_, D_, D_);
    gemm_tc<EP_QKV, 128><<<gProj, thr>>>(enc,  ca_Wv, ca_bv, nullptr, v, D_, D_, D_, D_);
    flash_k<<<gFl, thr, SMEM_FLASH_BYTES>>>(q, k, v, ctx);
    gemm_tc<EP_BIAS_RES, 128><<<gProj, thr>>>(ctx, ca_Wo, ca_bo, bufB, bufA, D_, D_, D_, D_);
    mvln_k<<<gMv, thr>>>(bufA, bufB, n2_g, n2_b);

    // ===================== feed-forward =====================
    gemm_tc<EP_GELU, 128><<<gFF1, thr>>>(bufB, ff_W1, ff_b1, nullptr, ff, DFF_, D_, D_, D_);
    gemm_tc<EP_BIAS_RES, 128><<<gProj, thr>>>(ff, ff_W2, ff_b2, bufB, bufA, D_, DFF_, DFF_, DFF_);
    mvln_k<<<gMv, thr>>>(bufA, out, n3_g, n3_b);
}